// round 12
// baseline (speedup 1.0000x reference)
#include <cuda_runtime.h>
#include <cuda_bf16.h>
#include <cstdint>
#include <math.h>

#define B_  2048
#define K_  16
#define M_  16
#define D_  256
#define NITER  20
#define MESHIT 3
#define RTOT   65536           // 2048*16 (q rows) + 2048*16 (r rows)

// ---------------- scratch (__device__ globals; no runtime alloc) ----------------
__device__ __nv_bfloat16 g_W1h[D_ * D_], g_W1l[D_ * D_];
__device__ __nv_bfloat16 g_W2h[D_ * D_], g_W2l[D_ * D_];
__device__ __nv_bfloat16 g_Hh[(size_t)RTOT * D_], g_Hl[(size_t)RTOT * D_];
__device__ float         g_P [(size_t)RTOT * D_];
__device__ int           g_flag[512];          // per-128-row-block L1 completion

// ---------------- helpers ----------------
__device__ __forceinline__ uint32_t smem_u32(const void* p) {
    uint32_t a;
    asm("{ .reg .u64 t; cvta.to.shared.u64 t, %1; cvt.u32.u64 %0, t; }" : "=r"(a) : "l"(p));
    return a;
}
__device__ __forceinline__ void cp16(uint32_t dst, const void* src) {
    asm volatile("cp.async.cg.shared.global [%0], [%1], 16;" :: "r"(dst), "l"(src) : "memory");
}
__device__ __forceinline__ void cp_commit() {
    asm volatile("cp.async.commit_group;" ::: "memory");
}
__device__ __forceinline__ void cp_wait0() {
    asm volatile("cp.async.wait_group 0;" ::: "memory");
}
__device__ __forceinline__ void ldm_x4(uint32_t* r, uint32_t addr) {
    asm volatile("ldmatrix.sync.aligned.m8n8.x4.shared.b16 {%0,%1,%2,%3}, [%4];"
                 : "=r"(r[0]), "=r"(r[1]), "=r"(r[2]), "=r"(r[3]) : "r"(addr));
}
__device__ __forceinline__ void mma_bf16(float* d, const uint32_t* a, const uint32_t* b) {
    asm volatile(
        "mma.sync.aligned.m16n8k16.row.col.f32.bf16.bf16.f32 "
        "{%0,%1,%2,%3}, {%4,%5,%6,%7}, {%8,%9}, {%0,%1,%2,%3};"
        : "+f"(d[0]), "+f"(d[1]), "+f"(d[2]), "+f"(d[3])
        : "r"(a[0]), "r"(a[1]), "r"(a[2]), "r"(a[3]), "r"(b[0]), "r"(b[1]));
}
__device__ __forceinline__ void split2(float a, float b, uint32_t& hi, uint32_t& lo) {
    __nv_bfloat16 ha = __float2bfloat16_rn(a), hb = __float2bfloat16_rn(b);
    float la = a - __bfloat162float(ha);
    float lb = b - __bfloat162float(hb);
    __nv_bfloat162 H; H.x = ha; H.y = hb;
    __nv_bfloat162 L; L.x = __float2bfloat16_rn(la); L.y = __float2bfloat16_rn(lb);
    hi = *reinterpret_cast<uint32_t*>(&H);
    lo = *reinterpret_cast<uint32_t*>(&L);
}

// ---------------- prep: zero flags + split weights ----------------
__global__ void reset_flags_kernel() { g_flag[threadIdx.x] = 0; }

__global__ void split_w_kernel(const float* __restrict__ W1, const float* __restrict__ W2) {
    int i = blockIdx.x * blockDim.x + threadIdx.x;
    float w1 = W1[i];
    __nv_bfloat16 h1 = __float2bfloat16_rn(w1);
    g_W1h[i] = h1;
    g_W1l[i] = __float2bfloat16_rn(w1 - __bfloat162float(h1));
    float w2 = W2[i];
    __nv_bfloat16 h2 = __float2bfloat16_rn(w2);
    g_W2h[i] = h2;
    g_W2l[i] = __float2bfloat16_rn(w2 - __bfloat162float(h2));
}

// ---------------- merged 2-layer GEMM: one launch, per-row-block flags ----------------
// bid < 1024:   layer-1 tile  (bidx = bid>>1, coly = bid&1)
// bid >= 1024:  layer-2 tile  (same mapping on bid-1024), spins on g_flag[bidx]==2.
#define OFF_AH 0
#define OFF_AL 8192
#define OFF_BH 16384
#define OFF_BL 24576
#define STAGE  32768
#define OFF_BIAS 65536
#define SMEM_SZ 66048

__device__ __forceinline__ uint32_t tile_addr(uint32_t base, int row, int c16) {
    int p = c16 ^ ((row >> 1) & 3);
    return base + row * 64 + p * 16;
}

__global__ void __launch_bounds__(256, 2) gemm_fused(
    const float* __restrict__ Aq, const float* __restrict__ Ar,
    const float* __restrict__ b1, const float* __restrict__ b2)
{
    extern __shared__ char smem[];
    const uint32_t sb = smem_u32(smem);
    const int tid  = threadIdx.x;
    const int w    = tid >> 5;
    const int lane = tid & 31;
    const int bid  = blockIdx.x;
    const bool layer1 = (bid < 1024);
    const int sub  = layer1 ? bid : bid - 1024;
    const int bidx = sub >> 1;
    const int col0 = (sub & 1) * 128;

    // L2 consumers wait for both L1 col-halves of this row block
    if (!layer1) {
        if (tid == 0) {
            while (atomicAdd(&g_flag[bidx], 0) < 2) { }
            __threadfence();
        }
        __syncthreads();
    }

    const __nv_bfloat16* Wh = layer1 ? g_W1h : g_W2h;
    const __nv_bfloat16* Wl = layer1 ? g_W1l : g_W2l;
    const float* bias = layer1 ? b1 : b2;
    const float* Asrc = nullptr;
    const __nv_bfloat16 *Ah = nullptr, *Al = nullptr;
    if (layer1) {
        Asrc = (bidx < 256) ? (Aq + (size_t)bidx * 128 * D_)
                            : (Ar + (size_t)(bidx - 256) * 128 * D_);
    } else {
        Ah = g_Hh + (size_t)bidx * 128 * D_;
        Al = g_Hl + (size_t)bidx * 128 * D_;
    }

    if (tid < 128) ((float*)(smem + OFF_BIAS))[tid] = bias[col0 + tid];

    const int lr   = tid >> 1;
    const int half = tid & 1;

    auto issue_loads = [&](int kc, int stage, float4* fa) {
        const uint32_t st = sb + stage * STAGE;
        const int k0 = kc * 32;
        {
            const __nv_bfloat16* sh = Wh + (size_t)(col0 + lr) * D_ + k0 + half * 16;
            const __nv_bfloat16* sl = Wl + (size_t)(col0 + lr) * D_ + k0 + half * 16;
            int c0 = half * 2;
            cp16(tile_addr(st + OFF_BH, lr, c0),     sh);
            cp16(tile_addr(st + OFF_BH, lr, c0 + 1), sh + 8);
            cp16(tile_addr(st + OFF_BL, lr, c0),     sl);
            cp16(tile_addr(st + OFF_BL, lr, c0 + 1), sl + 8);
        }
        if (!layer1) {
            const __nv_bfloat16* sh = Ah + (size_t)lr * D_ + k0 + half * 16;
            const __nv_bfloat16* sl = Al + (size_t)lr * D_ + k0 + half * 16;
            int c0 = half * 2;
            cp16(tile_addr(st + OFF_AH, lr, c0),     sh);
            cp16(tile_addr(st + OFF_AH, lr, c0 + 1), sh + 8);
            cp16(tile_addr(st + OFF_AL, lr, c0),     sl);
            cp16(tile_addr(st + OFF_AL, lr, c0 + 1), sl + 8);
        } else {
            const float4* p = reinterpret_cast<const float4*>(
                Asrc + (size_t)lr * D_ + k0 + half * 16);
            fa[0] = p[0]; fa[1] = p[1]; fa[2] = p[2]; fa[3] = p[3];
        }
        cp_commit();
    };
    auto sts_A = [&](int stage, const float4* fa) {
        const uint32_t st = sb + stage * STAGE;
        uint32_t h[8], l[8];
        split2(fa[0].x, fa[0].y, h[0], l[0]); split2(fa[0].z, fa[0].w, h[1], l[1]);
        split2(fa[1].x, fa[1].y, h[2], l[2]); split2(fa[1].z, fa[1].w, h[3], l[3]);
        split2(fa[2].x, fa[2].y, h[4], l[4]); split2(fa[2].z, fa[2].w, h[5], l[5]);
        split2(fa[3].x, fa[3].y, h[6], l[6]); split2(fa[3].z, fa[3].w, h[7], l[7]);
        int c0 = half * 2;
        *reinterpret_cast<uint4*>(smem + (tile_addr(st + OFF_AH, lr, c0)     - sb)) = make_uint4(h[0], h[1], h[2], h[3]);
        *reinterpret_cast<uint4*>(smem + (tile_addr(st + OFF_AH, lr, c0 + 1) - sb)) = make_uint4(h[4], h[5], h[6], h[7]);
        *reinterpret_cast<uint4*>(smem + (tile_addr(st + OFF_AL, lr, c0)     - sb)) = make_uint4(l[0], l[1], l[2], l[3]);
        *reinterpret_cast<uint4*>(smem + (tile_addr(st + OFF_AL, lr, c0 + 1) - sb)) = make_uint4(l[4], l[5], l[6], l[7]);
    };

    float4 fa[4];
    issue_loads(0, 0, fa);
    if (layer1) sts_A(0, fa);
    cp_wait0();
    __syncthreads();

    const int m0  = (w & 1) * 64;
    const int n0w = (w >> 1) * 32;
    float acc[4][4][4];
#pragma unroll
    for (int i = 0; i < 4; i++)
#pragma unroll
        for (int j = 0; j < 4; j++)
#pragma unroll
            for (int t = 0; t < 4; t++) acc[i][j][t] = 0.f;

    const int arow = m0 + (lane & 15);
    const int adc  = (lane >> 4) & 1;
    const int brow = n0w + ((lane >> 4) & 1) * 8 + (lane & 7);
    const int bdc  = (lane >> 3) & 1;

    for (int kc = 0; kc < 8; kc++) {
        const int cur = kc & 1, nxt = cur ^ 1;
        if (kc < 7) issue_loads(kc + 1, nxt, fa);

        const uint32_t st = sb + cur * STAGE;
#pragma unroll
        for (int ks = 0; ks < 2; ks++) {
            const int cb = ks * 2;
            uint32_t bh[8], bl[8], a[16];
#pragma unroll
            for (int pr = 0; pr < 2; pr++) {
                ldm_x4(bh + pr * 4, tile_addr(st + OFF_BH, brow + pr * 16, cb + bdc));
                ldm_x4(bl + pr * 4, tile_addr(st + OFF_BL, brow + pr * 16, cb + bdc));
            }
#pragma unroll
            for (int mt = 0; mt < 4; mt++)
                ldm_x4(a + mt * 4, tile_addr(st + OFF_AH, arow + mt * 16, cb + adc));
#pragma unroll
            for (int mt = 0; mt < 4; mt++)
#pragma unroll
                for (int nt = 0; nt < 4; nt++)
                    mma_bf16(acc[mt][nt], a + mt * 4, bh + nt * 2);
#pragma unroll
            for (int mt = 0; mt < 4; mt++)
#pragma unroll
                for (int nt = 0; nt < 4; nt++)
                    mma_bf16(acc[mt][nt], a + mt * 4, bl + nt * 2);
#pragma unroll
            for (int mt = 0; mt < 4; mt++)
                ldm_x4(a + mt * 4, tile_addr(st + OFF_AL, arow + mt * 16, cb + adc));
#pragma unroll
            for (int mt = 0; mt < 4; mt++)
#pragma unroll
                for (int nt = 0; nt < 4; nt++)
                    mma_bf16(acc[mt][nt], a + mt * 4, bh + nt * 2);
        }

        if (layer1 && kc < 7) sts_A(nxt, fa);
        cp_wait0();
        __syncthreads();
    }

    const float* sbias = (const float*)(smem + OFF_BIAS);
    const int g  = lane >> 2;
    const int tg = lane & 3;
#pragma unroll
    for (int mt = 0; mt < 4; mt++) {
        const int row0 = bidx * 128 + m0 + mt * 16 + g;
#pragma unroll
        for (int nt = 0; nt < 4; nt++) {
            const int ncl = n0w + nt * 8 + tg * 2;
            const int nc  = col0 + ncl;
            const float b0 = sbias[ncl], b1v = sbias[ncl + 1];
            float y0 = acc[mt][nt][0] + b0, y1 = acc[mt][nt][1] + b1v;
            float y2 = acc[mt][nt][2] + b0, y3 = acc[mt][nt][3] + b1v;
            if (layer1) {
                y0 = fmaxf(y0, 0.f); y1 = fmaxf(y1, 0.f);
                y2 = fmaxf(y2, 0.f); y3 = fmaxf(y3, 0.f);
                uint32_t h0, l0, h1, l1;
                split2(y0, y1, h0, l0);
                split2(y2, y3, h1, l1);
                *reinterpret_cast<uint32_t*>(g_Hh + (size_t)row0 * D_ + nc)       = h0;
                *reinterpret_cast<uint32_t*>(g_Hl + (size_t)row0 * D_ + nc)       = l0;
                *reinterpret_cast<uint32_t*>(g_Hh + (size_t)(row0 + 8) * D_ + nc) = h1;
                *reinterpret_cast<uint32_t*>(g_Hl + (size_t)(row0 + 8) * D_ + nc) = l1;
            } else {
                *reinterpret_cast<float2*>(g_P + (size_t)row0 * D_ + nc)       = make_float2(y0, y1);
                *reinterpret_cast<float2*>(g_P + (size_t)(row0 + 8) * D_ + nc) = make_float2(y2, y3);
            }
        }
    }

    // L1: publish completion of this col-half for the row block
    if (layer1) {
        __threadfence();
        __syncthreads();
        if (tid == 0) atomicAdd(&g_flag[bidx], 1);
    }
}

// ---------------- cost + sinkhorn fused: R11 cost, then warp0 runs sinkhorn --------
#define COST_CB 2
#define CROW 258
#define COST_MAT (16 * CROW)
#define OFF_CSM (COST_CB * 2 * COST_MAT + 2 * COST_CB * 16)     // C staging [2][256]
#define COST_SMEM ((OFF_CSM + 2 * 256) * 4)

__global__ void __launch_bounds__(256) cost_sink_kernel(
    const float* __restrict__ mask_q, const float* __restrict__ mask_r,
    float* __restrict__ out_sim, float* __restrict__ out_T,
    float* __restrict__ out_C,   float* __restrict__ out_cost)
{
    extern __shared__ float sm[];
    const int tid = threadIdx.x;
    const int b0  = blockIdx.x * COST_CB;
    const uint32_t FULL = 0xffffffffu;

#pragma unroll
    for (int it = 0; it < 16; it++) {
        int u   = tid + it * 256;
        int mat = u >> 10;
        int v   = u & 1023;
        int blb = mat >> 1, isr = mat & 1;
        int row = v >> 6, d = (v & 63) * 4;
        const float* src = g_P + ((size_t)(isr ? 32768 : 0) + (size_t)(b0 + blb) * 16 + row) * 256 + d;
        float4 x = *reinterpret_cast<const float4*>(src);
        float* dst = sm + (blb * 2 + isr) * COST_MAT + row * CROW + d;
        dst[0] = x.x; dst[1] = x.y; dst[2] = x.z; dst[3] = x.w;
    }
    __syncthreads();

    const int bl = tid >> 7, t = tid & 127;
    const float* q = sm + bl * 2 * COST_MAT;
    const float* r = q + COST_MAT;
    float* nq  = sm + COST_CB * 2 * COST_MAT;
    float* nr  = nq + COST_CB * 16;
    float* Csm = sm + OFF_CSM;

    if (t < 64) {
        int row = t & 15;
        int h   = (t >> 4) & 1;
        int isr = (t >> 5) & 1;
        const float* src = (isr ? r : q) + row * CROW;
        float s0 = 0.f, s1 = 0.f;
#pragma unroll 8
        for (int d = 2 * h; d < 256; d += 4) {
            float2 x = *reinterpret_cast<const float2*>(src + d);
            s0 = fmaf(x.x, x.x, s0);
            s1 = fmaf(x.y, x.y, s1);
        }
        float s = s0 + s1;
        s += __shfl_xor_sync(FULL, s, 16);
        if (h == 0) (isr ? nr : nq)[bl * 16 + row] = s;
    }

    const int m2 = t & 7;
    const int dh = (t >> 3) & 1;
    const int k2 = t >> 4;
    const float* qa = q + (2 * k2) * CROW;
    const float* qb = qa + CROW;
    const float* ra = r + (2 * m2) * CROW;
    const float* rb = ra + CROW;
    float g00 = 0.f, g01 = 0.f, g10 = 0.f, g11 = 0.f;
#pragma unroll 8
    for (int d = 2 * dh; d < 256; d += 4) {
        float2 xa = *reinterpret_cast<const float2*>(qa + d);
        float2 xb = *reinterpret_cast<const float2*>(qb + d);
        float2 ya = *reinterpret_cast<const float2*>(ra + d);
        float2 yb = *reinterpret_cast<const float2*>(rb + d);
        g00 = fmaf(xa.x, ya.x, g00); g00 = fmaf(xa.y, ya.y, g00);
        g01 = fmaf(xa.x, yb.x, g01); g01 = fmaf(xa.y, yb.y, g01);
        g10 = fmaf(xb.x, ya.x, g10); g10 = fmaf(xb.y, ya.y, g10);
        g11 = fmaf(xb.x, yb.x, g11); g11 = fmaf(xb.y, yb.y, g11);
    }
    g00 += __shfl_xor_sync(FULL, g00, 8);
    g01 += __shfl_xor_sync(FULL, g01, 8);
    g10 += __shfl_xor_sync(FULL, g10, 8);
    g11 += __shfl_xor_sync(FULL, g11, 8);
    __syncthreads();

    if (dh == 0) {
        const float nqa = nq[bl * 16 + 2 * k2], nqb = nq[bl * 16 + 2 * k2 + 1];
        const float nra = nr[bl * 16 + 2 * m2], nrb = nr[bl * 16 + 2 * m2 + 1];
        float c00 = sqrtf(fmaxf(nqa + nra - 2.f * g00, 1e-6f));
        float c01 = sqrtf(fmaxf(nqa + nrb - 2.f * g01, 1e-6f));
        float c10 = sqrtf(fmaxf(nqb + nra - 2.f * g10, 1e-6f));
        float c11 = sqrtf(fmaxf(nqb + nrb - 2.f * g11, 1e-6f));
        float* Co = out_C + (size_t)(b0 + bl) * 256;
        Co[(2 * k2)     * 16 + 2 * m2]     = c00;
        Co[(2 * k2)     * 16 + 2 * m2 + 1] = c01;
        Co[(2 * k2 + 1) * 16 + 2 * m2]     = c10;
        Co[(2 * k2 + 1) * 16 + 2 * m2 + 1] = c11;
        float* Cs = Csm + bl * 256;
        Cs[(2 * k2)     * 16 + 2 * m2]     = c00;
        Cs[(2 * k2)     * 16 + 2 * m2 + 1] = c01;
        Cs[(2 * k2 + 1) * 16 + 2 * m2]     = c10;
        Cs[(2 * k2 + 1) * 16 + 2 * m2 + 1] = c11;
    }
    __syncthreads();

    // ---- warp 0: linear Sinkhorn + MESH for the 2 batches (half-warp each) ----
    if (tid < 32) {
        const int lane = tid;
        const int half = lane >> 4;
        const int j    = lane & 15;
        const int b    = b0 + half;
        const float* Cb = Csm + half * 256;

        float Crow[16], Ccol[16];
#pragma unroll
        for (int i = 0; i < 16; i++) Crow[i] = Cb[j * 16 + i];
#pragma unroll
        for (int k = 0; k < 16; k++) Ccol[k] = Cb[k * 16 + j];

        float lmq = __logf(fmaxf(mask_q[b * 16 + j], 1e-8f));
        float lmr = __logf(fmaxf(mask_r[b * 16 + j], 1e-8f));
        float mq = lmq, mr = lmr;
#pragma unroll
        for (int s = 1; s < 16; s <<= 1) {
            mq = fmaxf(mq, __shfl_xor_sync(FULL, mq, s, 16));
            mr = fmaxf(mr, __shfl_xor_sync(FULL, mr, s, 16));
        }
        float eq = __expf(lmq - mq), er = __expf(lmr - mr);
#pragma unroll
        for (int s = 1; s < 16; s <<= 1) {
            eq += __shfl_xor_sync(FULL, eq, s, 16);
            er += __shfl_xor_sync(FULL, er, s, 16);
        }
        const float logmu = lmq - (mq + __logf(eq));
        const float lognu = lmr - (mr + __logf(er));

        float mv[16], nv[16];
#pragma unroll
        for (int i = 0; i < 16; i++) {
            mv[i] = __shfl_sync(FULL, logmu, i, 16);
            nv[i] = __shfl_sync(FULL, lognu, i, 16);
        }

        float Erow[16], Ecol[16];
#pragma unroll
        for (int i = 0; i < 16; i++) Erow[i] = -Crow[i] / 0.05f + logmu + nv[i];
        float mx = Erow[0];
#pragma unroll
        for (int i = 1; i < 16; i++) mx = fmaxf(mx, Erow[i]);
#pragma unroll
        for (int s = 1; s < 16; s <<= 1) mx = fmaxf(mx, __shfl_xor_sync(FULL, mx, s, 16));
#pragma unroll
        for (int i = 0; i < 16; i++) Erow[i] = __expf(Erow[i] - mx);
#pragma unroll
        for (int k = 0; k < 16; k++) Ecol[k] = __expf(-Ccol[k] / 0.05f + mv[k] + lognu - mx);

        float bv[16];
#pragma unroll
        for (int i = 0; i < 16; i++) bv[i] = 1.f;
        float a = 1.f;
        for (int it = 0; it < NITER; it++) {
            float s0 = 0.f, s1 = 0.f, s2 = 0.f, s3 = 0.f;
#pragma unroll
            for (int i = 0; i < 16; i += 4) {
                s0 = fmaf(Erow[i],     bv[i],     s0);
                s1 = fmaf(Erow[i + 1], bv[i + 1], s1);
                s2 = fmaf(Erow[i + 2], bv[i + 2], s2);
                s3 = fmaf(Erow[i + 3], bv[i + 3], s3);
            }
            a = __fdividef(1.f, (s0 + s1) + (s2 + s3));
            float av[16];
#pragma unroll
            for (int i = 0; i < 16; i++) av[i] = __shfl_sync(FULL, a, i, 16);
            float t0 = 0.f, t1 = 0.f, t2 = 0.f, t3 = 0.f;
#pragma unroll
            for (int k = 0; k < 16; k += 4) {
                t0 = fmaf(Ecol[k],     av[k],     t0);
                t1 = fmaf(Ecol[k + 1], av[k + 1], t1);
                t2 = fmaf(Ecol[k + 2], av[k + 2], t2);
                t3 = fmaf(Ecol[k + 3], av[k + 3], t3);
            }
            float bb = __fdividef(1.f, (t0 + t1) + (t2 + t3));
#pragma unroll
            for (int i = 0; i < 16; i++) bv[i] = __shfl_sync(FULL, bb, i, 16);
        }

        float T[16];
#pragma unroll
        for (int i = 0; i < 16; i++) T[i] = a * Erow[i] * bv[i];

#pragma unroll
        for (int it = 0; it < MESHIT; it++) {
            float rs = 0.f;
#pragma unroll
            for (int i = 0; i < 16; i++) { T[i] *= T[i]; rs += T[i]; }
            float inv = __fdividef(1.f, rs + 1e-8f);
            float cs[16];
#pragma unroll
            for (int i = 0; i < 16; i++) { T[i] *= inv; cs[i] = T[i]; }
#pragma unroll
            for (int s = 1; s < 16; s <<= 1)
#pragma unroll
                for (int i = 0; i < 16; i++) cs[i] += __shfl_xor_sync(FULL, cs[i], s, 16);
#pragma unroll
            for (int i = 0; i < 16; i++) T[i] = __fdividef(T[i], cs[i] + 1e-8f);
        }

        float tc = 0.f;
#pragma unroll
        for (int i = 0; i < 16; i++) tc = fmaf(T[i], Crow[i], tc);
#pragma unroll
        for (int s = 1; s < 16; s <<= 1) tc += __shfl_xor_sync(FULL, tc, s, 16);
        if (j == 0) {
            out_cost[b] = tc;
            out_sim[b]  = __fdividef(1.f, 1.f + __expf(tc));
        }
        float* To = out_T + (size_t)b * 256 + j * 16;
#pragma unroll
        for (int i = 0; i < 4; i++)
            *reinterpret_cast<float4*>(To + 4 * i) =
                make_float4(T[4 * i], T[4 * i + 1], T[4 * i + 2], T[4 * i + 3]);
    }
}

// ---------------------------------------------------------------------------
extern "C" void kernel_launch(void* const* d_in, const int* in_sizes, int n_in,
                              void* d_out, int out_size)
{
    const float* slots_q = (const float*)d_in[0];
    const float* slots_r = (const float*)d_in[1];
    const float* mask_q  = (const float*)d_in[2];
    const float* mask_r  = (const float*)d_in[3];
    const float* W1      = (const float*)d_in[4];
    const float* b1      = (const float*)d_in[5];
    const float* W2      = (const float*)d_in[6];
    const float* b2      = (const float*)d_in[7];

    float* out      = (float*)d_out;
    float* out_sim  = out;
    float* out_T    = out_sim + B_;
    float* out_C    = out_T + (size_t)B_ * K_ * M_;
    float* out_cost = out_C + (size_t)B_ * K_ * M_;

    cudaFuncSetAttribute(gemm_fused, cudaFuncAttributeMaxDynamicSharedMemorySize, SMEM_SZ);
    cudaFuncSetAttribute(cost_sink_kernel, cudaFuncAttributeMaxDynamicSharedMemorySize, COST_SMEM);

    reset_flags_kernel<<<1, 512>>>();
    split_w_kernel<<<128, 512>>>(W1, W2);
    gemm_fused<<<2048, 256, SMEM_SZ>>>(slots_q, slots_r, b1, b2);
    cost_sink_kernel<<<B_ / COST_CB, 256, COST_SMEM>>>(mask_q, mask_r,
                                                       out_sim, out_T, out_C, out_cost);
}

// round 13
// speedup vs baseline: 1.0176x; 1.0176x over previous
#include <cuda_runtime.h>
#include <cuda_bf16.h>
#include <cstdint>
#include <math.h>

#define B_  2048
#define K_  16
#define M_  16
#define D_  256
#define NITER  20
#define MESHIT 3
#define RTOT   65536           // 2048*16 (q rows) + 2048*16 (r rows)

// ---------------- scratch (__device__ globals; no runtime alloc) ----------------
__device__ __nv_bfloat16 g_W1h[D_ * D_], g_W1l[D_ * D_];
__device__ __nv_bfloat16 g_W2h[D_ * D_], g_W2l[D_ * D_];
__device__ __nv_bfloat16 g_Hh[(size_t)RTOT * D_], g_Hl[(size_t)RTOT * D_];
__device__ float         g_P [(size_t)RTOT * D_];
__device__ int           g_flag[512];          // per-128-row-block L1 completion

// ---------------- helpers ----------------
__device__ __forceinline__ uint32_t smem_u32(const void* p) {
    uint32_t a;
    asm("{ .reg .u64 t; cvta.to.shared.u64 t, %1; cvt.u32.u64 %0, t; }" : "=r"(a) : "l"(p));
    return a;
}
__device__ __forceinline__ void cp16(uint32_t dst, const void* src) {
    asm volatile("cp.async.cg.shared.global [%0], [%1], 16;" :: "r"(dst), "l"(src) : "memory");
}
__device__ __forceinline__ void cp_commit() {
    asm volatile("cp.async.commit_group;" ::: "memory");
}
__device__ __forceinline__ void cp_wait0() {
    asm volatile("cp.async.wait_group 0;" ::: "memory");
}
__device__ __forceinline__ void ldm_x4(uint32_t* r, uint32_t addr) {
    asm volatile("ldmatrix.sync.aligned.m8n8.x4.shared.b16 {%0,%1,%2,%3}, [%4];"
                 : "=r"(r[0]), "=r"(r[1]), "=r"(r[2]), "=r"(r[3]) : "r"(addr));
}
__device__ __forceinline__ void mma_bf16(float* d, const uint32_t* a, const uint32_t* b) {
    asm volatile(
        "mma.sync.aligned.m16n8k16.row.col.f32.bf16.bf16.f32 "
        "{%0,%1,%2,%3}, {%4,%5,%6,%7}, {%8,%9}, {%0,%1,%2,%3};"
        : "+f"(d[0]), "+f"(d[1]), "+f"(d[2]), "+f"(d[3])
        : "r"(a[0]), "r"(a[1]), "r"(a[2]), "r"(a[3]), "r"(b[0]), "r"(b[1]));
}
__device__ __forceinline__ void split2(float a, float b, uint32_t& hi, uint32_t& lo) {
    __nv_bfloat16 ha = __float2bfloat16_rn(a), hb = __float2bfloat16_rn(b);
    float la = a - __bfloat162float(ha);
    float lb = b - __bfloat162float(hb);
    __nv_bfloat162 H; H.x = ha; H.y = hb;
    __nv_bfloat162 L; L.x = __float2bfloat16_rn(la); L.y = __float2bfloat16_rn(lb);
    hi = *reinterpret_cast<uint32_t*>(&H);
    lo = *reinterpret_cast<uint32_t*>(&L);
}

// ---------------- prep: zero flags + split weights ----------------
__global__ void reset_flags_kernel() { g_flag[threadIdx.x] = 0; }

__global__ void split_w_kernel(const float* __restrict__ W1, const float* __restrict__ W2) {
    int i = blockIdx.x * blockDim.x + threadIdx.x;
    float w1 = W1[i];
    __nv_bfloat16 h1 = __float2bfloat16_rn(w1);
    g_W1h[i] = h1;
    g_W1l[i] = __float2bfloat16_rn(w1 - __bfloat162float(h1));
    float w2 = W2[i];
    __nv_bfloat16 h2 = __float2bfloat16_rn(w2);
    g_W2h[i] = h2;
    g_W2l[i] = __float2bfloat16_rn(w2 - __bfloat162float(h2));
}

// ---------------- merged 2-layer GEMM: one launch, per-row-block flags ----------------
#define OFF_AH 0
#define OFF_AL 8192
#define OFF_BH 16384
#define OFF_BL 24576
#define STAGE  32768
#define OFF_BIAS 65536
#define SMEM_SZ 66048

__device__ __forceinline__ uint32_t tile_addr(uint32_t base, int row, int c16) {
    int p = c16 ^ ((row >> 1) & 3);
    return base + row * 64 + p * 16;
}

__global__ void __launch_bounds__(256, 2) gemm_fused(
    const float* __restrict__ Aq, const float* __restrict__ Ar,
    const float* __restrict__ b1, const float* __restrict__ b2)
{
    extern __shared__ char smem[];
    const uint32_t sb = smem_u32(smem);
    const int tid  = threadIdx.x;
    const int w    = tid >> 5;
    const int lane = tid & 31;
    const int bid  = blockIdx.x;
    const bool layer1 = (bid < 1024);
    const int sub  = layer1 ? bid : bid - 1024;
    const int bidx = sub >> 1;
    const int col0 = (sub & 1) * 128;

    if (!layer1) {
        if (tid == 0) {
            while (atomicAdd(&g_flag[bidx], 0) < 2) { }
            __threadfence();
        }
        __syncthreads();
    }

    const __nv_bfloat16* Wh = layer1 ? g_W1h : g_W2h;
    const __nv_bfloat16* Wl = layer1 ? g_W1l : g_W2l;
    const float* bias = layer1 ? b1 : b2;
    const float* Asrc = nullptr;
    const __nv_bfloat16 *Ah = nullptr, *Al = nullptr;
    if (layer1) {
        Asrc = (bidx < 256) ? (Aq + (size_t)bidx * 128 * D_)
                            : (Ar + (size_t)(bidx - 256) * 128 * D_);
    } else {
        Ah = g_Hh + (size_t)bidx * 128 * D_;
        Al = g_Hl + (size_t)bidx * 128 * D_;
    }

    if (tid < 128) ((float*)(smem + OFF_BIAS))[tid] = bias[col0 + tid];

    const int lr   = tid >> 1;
    const int half = tid & 1;

    auto issue_loads = [&](int kc, int stage, float4* fa) {
        const uint32_t st = sb + stage * STAGE;
        const int k0 = kc * 32;
        {
            const __nv_bfloat16* sh = Wh + (size_t)(col0 + lr) * D_ + k0 + half * 16;
            const __nv_bfloat16* sl = Wl + (size_t)(col0 + lr) * D_ + k0 + half * 16;
            int c0 = half * 2;
            cp16(tile_addr(st + OFF_BH, lr, c0),     sh);
            cp16(tile_addr(st + OFF_BH, lr, c0 + 1), sh + 8);
            cp16(tile_addr(st + OFF_BL, lr, c0),     sl);
            cp16(tile_addr(st + OFF_BL, lr, c0 + 1), sl + 8);
        }
        if (!layer1) {
            const __nv_bfloat16* sh = Ah + (size_t)lr * D_ + k0 + half * 16;
            const __nv_bfloat16* sl = Al + (size_t)lr * D_ + k0 + half * 16;
            int c0 = half * 2;
            cp16(tile_addr(st + OFF_AH, lr, c0),     sh);
            cp16(tile_addr(st + OFF_AH, lr, c0 + 1), sh + 8);
            cp16(tile_addr(st + OFF_AL, lr, c0),     sl);
            cp16(tile_addr(st + OFF_AL, lr, c0 + 1), sl + 8);
        } else {
            const float4* p = reinterpret_cast<const float4*>(
                Asrc + (size_t)lr * D_ + k0 + half * 16);
            fa[0] = p[0]; fa[1] = p[1]; fa[2] = p[2]; fa[3] = p[3];
        }
        cp_commit();
    };
    auto sts_A = [&](int stage, const float4* fa) {
        const uint32_t st = sb + stage * STAGE;
        uint32_t h[8], l[8];
        split2(fa[0].x, fa[0].y, h[0], l[0]); split2(fa[0].z, fa[0].w, h[1], l[1]);
        split2(fa[1].x, fa[1].y, h[2], l[2]); split2(fa[1].z, fa[1].w, h[3], l[3]);
        split2(fa[2].x, fa[2].y, h[4], l[4]); split2(fa[2].z, fa[2].w, h[5], l[5]);
        split2(fa[3].x, fa[3].y, h[6], l[6]); split2(fa[3].z, fa[3].w, h[7], l[7]);
        int c0 = half * 2;
        *reinterpret_cast<uint4*>(smem + (tile_addr(st + OFF_AH, lr, c0)     - sb)) = make_uint4(h[0], h[1], h[2], h[3]);
        *reinterpret_cast<uint4*>(smem + (tile_addr(st + OFF_AH, lr, c0 + 1) - sb)) = make_uint4(h[4], h[5], h[6], h[7]);
        *reinterpret_cast<uint4*>(smem + (tile_addr(st + OFF_AL, lr, c0)     - sb)) = make_uint4(l[0], l[1], l[2], l[3]);
        *reinterpret_cast<uint4*>(smem + (tile_addr(st + OFF_AL, lr, c0 + 1) - sb)) = make_uint4(l[4], l[5], l[6], l[7]);
    };

    float4 fa[4];
    issue_loads(0, 0, fa);
    if (layer1) sts_A(0, fa);
    cp_wait0();
    __syncthreads();

    const int m0  = (w & 1) * 64;
    const int n0w = (w >> 1) * 32;
    float acc[4][4][4];
#pragma unroll
    for (int i = 0; i < 4; i++)
#pragma unroll
        for (int j = 0; j < 4; j++)
#pragma unroll
            for (int t = 0; t < 4; t++) acc[i][j][t] = 0.f;

    const int arow = m0 + (lane & 15);
    const int adc  = (lane >> 4) & 1;
    const int brow = n0w + ((lane >> 4) & 1) * 8 + (lane & 7);
    const int bdc  = (lane >> 3) & 1;

    for (int kc = 0; kc < 8; kc++) {
        const int cur = kc & 1, nxt = cur ^ 1;
        if (kc < 7) issue_loads(kc + 1, nxt, fa);

        const uint32_t st = sb + cur * STAGE;
#pragma unroll
        for (int ks = 0; ks < 2; ks++) {
            const int cb = ks * 2;
            uint32_t bh[8], bl[8], a[16];
#pragma unroll
            for (int pr = 0; pr < 2; pr++) {
                ldm_x4(bh + pr * 4, tile_addr(st + OFF_BH, brow + pr * 16, cb + bdc));
                ldm_x4(bl + pr * 4, tile_addr(st + OFF_BL, brow + pr * 16, cb + bdc));
            }
#pragma unroll
            for (int mt = 0; mt < 4; mt++)
                ldm_x4(a + mt * 4, tile_addr(st + OFF_AH, arow + mt * 16, cb + adc));
#pragma unroll
            for (int mt = 0; mt < 4; mt++)
#pragma unroll
                for (int nt = 0; nt < 4; nt++)
                    mma_bf16(acc[mt][nt], a + mt * 4, bh + nt * 2);
#pragma unroll
            for (int mt = 0; mt < 4; mt++)
#pragma unroll
                for (int nt = 0; nt < 4; nt++)
                    mma_bf16(acc[mt][nt], a + mt * 4, bl + nt * 2);
#pragma unroll
            for (int mt = 0; mt < 4; mt++)
                ldm_x4(a + mt * 4, tile_addr(st + OFF_AL, arow + mt * 16, cb + adc));
#pragma unroll
            for (int mt = 0; mt < 4; mt++)
#pragma unroll
                for (int nt = 0; nt < 4; nt++)
                    mma_bf16(acc[mt][nt], a + mt * 4, bh + nt * 2);
        }

        if (layer1 && kc < 7) sts_A(nxt, fa);
        cp_wait0();
        __syncthreads();
    }

    const float* sbias = (const float*)(smem + OFF_BIAS);
    const int g  = lane >> 2;
    const int tg = lane & 3;
#pragma unroll
    for (int mt = 0; mt < 4; mt++) {
        const int row0 = bidx * 128 + m0 + mt * 16 + g;
#pragma unroll
        for (int nt = 0; nt < 4; nt++) {
            const int ncl = n0w + nt * 8 + tg * 2;
            const int nc  = col0 + ncl;
            const float b0 = sbias[ncl], b1v = sbias[ncl + 1];
            float y0 = acc[mt][nt][0] + b0, y1 = acc[mt][nt][1] + b1v;
            float y2 = acc[mt][nt][2] + b0, y3 = acc[mt][nt][3] + b1v;
            if (layer1) {
                y0 = fmaxf(y0, 0.f); y1 = fmaxf(y1, 0.f);
                y2 = fmaxf(y2, 0.f); y3 = fmaxf(y3, 0.f);
                uint32_t h0, l0, h1, l1;
                split2(y0, y1, h0, l0);
                split2(y2, y3, h1, l1);
                *reinterpret_cast<uint32_t*>(g_Hh + (size_t)row0 * D_ + nc)       = h0;
                *reinterpret_cast<uint32_t*>(g_Hl + (size_t)row0 * D_ + nc)       = l0;
                *reinterpret_cast<uint32_t*>(g_Hh + (size_t)(row0 + 8) * D_ + nc) = h1;
                *reinterpret_cast<uint32_t*>(g_Hl + (size_t)(row0 + 8) * D_ + nc) = l1;
            } else {
                *reinterpret_cast<float2*>(g_P + (size_t)row0 * D_ + nc)       = make_float2(y0, y1);
                *reinterpret_cast<float2*>(g_P + (size_t)(row0 + 8) * D_ + nc) = make_float2(y2, y3);
            }
        }
    }

    if (layer1) {
        __threadfence();
        __syncthreads();
        if (tid == 0) atomicAdd(&g_flag[bidx], 1);
    }
}

// ---------------- cost kernel v5 (R11): smem Gram + split-d, 256 threads ----------
#define COST_CB 2
#define CROW 258
#define COST_MAT (16 * CROW)
#define COST_SMEM ((COST_CB * 2 * COST_MAT + 2 * COST_CB * 16) * 4)

__global__ void __launch_bounds__(256) cost_kernel(float* __restrict__ out_C)
{
    extern __shared__ float sm[];
    const int tid = threadIdx.x;
    const int b0  = blockIdx.x * COST_CB;
    const uint32_t FULL = 0xffffffffu;

#pragma unroll
    for (int it = 0; it < 16; it++) {
        int u   = tid + it * 256;
        int mat = u >> 10;
        int v   = u & 1023;
        int blb = mat >> 1, isr = mat & 1;
        int row = v >> 6, d = (v & 63) * 4;
        const float* src = g_P + ((size_t)(isr ? 32768 : 0) + (size_t)(b0 + blb) * 16 + row) * 256 + d;
        float4 x = *reinterpret_cast<const float4*>(src);
        float* dst = sm + (blb * 2 + isr) * COST_MAT + row * CROW + d;
        dst[0] = x.x; dst[1] = x.y; dst[2] = x.z; dst[3] = x.w;
    }
    __syncthreads();

    const int bl = tid >> 7, t = tid & 127;
    const float* q = sm + bl * 2 * COST_MAT;
    const float* r = q + COST_MAT;
    float* nq = sm + COST_CB * 2 * COST_MAT;
    float* nr = nq + COST_CB * 16;

    if (t < 64) {
        int row = t & 15;
        int h   = (t >> 4) & 1;
        int isr = (t >> 5) & 1;
        const float* src = (isr ? r : q) + row * CROW;
        float s0 = 0.f, s1 = 0.f;
#pragma unroll 8
        for (int d = 2 * h; d < 256; d += 4) {
            float2 x = *reinterpret_cast<const float2*>(src + d);
            s0 = fmaf(x.x, x.x, s0);
            s1 = fmaf(x.y, x.y, s1);
        }
        float s = s0 + s1;
        s += __shfl_xor_sync(FULL, s, 16);
        if (h == 0) (isr ? nr : nq)[bl * 16 + row] = s;
    }

    const int m2 = t & 7;
    const int dh = (t >> 3) & 1;
    const int k2 = t >> 4;
    const float* qa = q + (2 * k2) * CROW;
    const float* qb = qa + CROW;
    const float* ra = r + (2 * m2) * CROW;
    const float* rb = ra + CROW;
    float g00 = 0.f, g01 = 0.f, g10 = 0.f, g11 = 0.f;
#pragma unroll 8
    for (int d = 2 * dh; d < 256; d += 4) {
        float2 xa = *reinterpret_cast<const float2*>(qa + d);
        float2 xb = *reinterpret_cast<const float2*>(qb + d);
        float2 ya = *reinterpret_cast<const float2*>(ra + d);
        float2 yb = *reinterpret_cast<const float2*>(rb + d);
        g00 = fmaf(xa.x, ya.x, g00); g00 = fmaf(xa.y, ya.y, g00);
        g01 = fmaf(xa.x, yb.x, g01); g01 = fmaf(xa.y, yb.y, g01);
        g10 = fmaf(xb.x, ya.x, g10); g10 = fmaf(xb.y, ya.y, g10);
        g11 = fmaf(xb.x, yb.x, g11); g11 = fmaf(xb.y, yb.y, g11);
    }
    g00 += __shfl_xor_sync(FULL, g00, 8);
    g01 += __shfl_xor_sync(FULL, g01, 8);
    g10 += __shfl_xor_sync(FULL, g10, 8);
    g11 += __shfl_xor_sync(FULL, g11, 8);
    __syncthreads();

    if (dh == 0) {
        const float nqa = nq[bl * 16 + 2 * k2], nqb = nq[bl * 16 + 2 * k2 + 1];
        const float nra = nr[bl * 16 + 2 * m2], nrb = nr[bl * 16 + 2 * m2 + 1];
        float* Co = out_C + (size_t)(b0 + bl) * 256;
        Co[(2 * k2)     * 16 + 2 * m2]     = sqrtf(fmaxf(nqa + nra - 2.f * g00, 1e-6f));
        Co[(2 * k2)     * 16 + 2 * m2 + 1] = sqrtf(fmaxf(nqa + nrb - 2.f * g01, 1e-6f));
        Co[(2 * k2 + 1) * 16 + 2 * m2]     = sqrtf(fmaxf(nqb + nra - 2.f * g10, 1e-6f));
        Co[(2 * k2 + 1) * 16 + 2 * m2 + 1] = sqrtf(fmaxf(nqb + nrb - 2.f * g11, 1e-6f));
    }
}

// ---------------- sinkhorn iterate: linear domain, half-warp per batch ----------------
__global__ void __launch_bounds__(256) sinkhorn_iter(
    const float* __restrict__ C, const float* __restrict__ mask_q,
    const float* __restrict__ mask_r,
    float* __restrict__ out_sim, float* __restrict__ out_T,
    float* __restrict__ out_cost)
{
    const int tid  = threadIdx.x;
    const int wrp  = tid >> 5;
    const int lane = tid & 31;
    const int half = lane >> 4;
    const int j    = lane & 15;
    const int b    = blockIdx.x * 16 + wrp * 2 + half;
    const uint32_t FULL = 0xffffffffu;

    const float* Cb = C + (size_t)b * 256;
    float Crow[16], Ccol[16];
#pragma unroll
    for (int i = 0; i < 4; i++) {
        float4 v = *reinterpret_cast<const float4*>(Cb + j * 16 + i * 4);
        Crow[4 * i] = v.x; Crow[4 * i + 1] = v.y; Crow[4 * i + 2] = v.z; Crow[4 * i + 3] = v.w;
    }
#pragma unroll
    for (int k = 0; k < 16; k++) Ccol[k] = Cb[k * 16 + j];

    float lmq = __logf(fmaxf(mask_q[b * 16 + j], 1e-8f));
    float lmr = __logf(fmaxf(mask_r[b * 16 + j], 1e-8f));
    float mq = lmq, mr = lmr;
#pragma unroll
    for (int s = 1; s < 16; s <<= 1) {
        mq = fmaxf(mq, __shfl_xor_sync(FULL, mq, s, 16));
        mr = fmaxf(mr, __shfl_xor_sync(FULL, mr, s, 16));
    }
    float eq = __expf(lmq - mq), er = __expf(lmr - mr);
#pragma unroll
    for (int s = 1; s < 16; s <<= 1) {
        eq += __shfl_xor_sync(FULL, eq, s, 16);
        er += __shfl_xor_sync(FULL, er, s, 16);
    }
    const float logmu = lmq - (mq + __logf(eq));
    const float lognu = lmr - (mr + __logf(er));

    float mv[16], nv[16];
#pragma unroll
    for (int i = 0; i < 16; i++) {
        mv[i] = __shfl_sync(FULL, logmu, i, 16);
        nv[i] = __shfl_sync(FULL, lognu, i, 16);
    }

    float Erow[16], Ecol[16];
#pragma unroll
    for (int i = 0; i < 16; i++) Erow[i] = -Crow[i] / 0.05f + logmu + nv[i];
    float mx = Erow[0];
#pragma unroll
    for (int i = 1; i < 16; i++) mx = fmaxf(mx, Erow[i]);
#pragma unroll
    for (int s = 1; s < 16; s <<= 1) mx = fmaxf(mx, __shfl_xor_sync(FULL, mx, s, 16));
#pragma unroll
    for (int i = 0; i < 16; i++) Erow[i] = __expf(Erow[i] - mx);
#pragma unroll
    for (int k = 0; k < 16; k++) Ecol[k] = __expf(-Ccol[k] / 0.05f + mv[k] + lognu - mx);

    float bv[16];
#pragma unroll
    for (int i = 0; i < 16; i++) bv[i] = 1.f;
    float a = 1.f;
    for (int it = 0; it < NITER; it++) {
        float s0 = 0.f, s1 = 0.f, s2 = 0.f, s3 = 0.f;
#pragma unroll
        for (int i = 0; i < 16; i += 4) {
            s0 = fmaf(Erow[i],     bv[i],     s0);
            s1 = fmaf(Erow[i + 1], bv[i + 1], s1);
            s2 = fmaf(Erow[i + 2], bv[i + 2], s2);
            s3 = fmaf(Erow[i + 3], bv[i + 3], s3);
        }
        a = __fdividef(1.f, (s0 + s1) + (s2 + s3));
        float av[16];
#pragma unroll
        for (int i = 0; i < 16; i++) av[i] = __shfl_sync(FULL, a, i, 16);
        float t0 = 0.f, t1 = 0.f, t2 = 0.f, t3 = 0.f;
#pragma unroll
        for (int k = 0; k < 16; k += 4) {
            t0 = fmaf(Ecol[k],     av[k],     t0);
            t1 = fmaf(Ecol[k + 1], av[k + 1], t1);
            t2 = fmaf(Ecol[k + 2], av[k + 2], t2);
            t3 = fmaf(Ecol[k + 3], av[k + 3], t3);
        }
        float bb = __fdividef(1.f, (t0 + t1) + (t2 + t3));
#pragma unroll
        for (int i = 0; i < 16; i++) bv[i] = __shfl_sync(FULL, bb, i, 16);
    }

    float T[16];
#pragma unroll
    for (int i = 0; i < 16; i++) T[i] = a * Erow[i] * bv[i];

#pragma unroll
    for (int it = 0; it < MESHIT; it++) {
        float rs = 0.f;
#pragma unroll
        for (int i = 0; i < 16; i++) { T[i] *= T[i]; rs += T[i]; }
        float inv = __fdividef(1.f, rs + 1e-8f);
        float cs[16];
#pragma unroll
        for (int i = 0; i < 16; i++) { T[i] *= inv; cs[i] = T[i]; }
#pragma unroll
        for (int s = 1; s < 16; s <<= 1)
#pragma unroll
            for (int i = 0; i < 16; i++) cs[i] += __shfl_xor_sync(FULL, cs[i], s, 16);
#pragma unroll
        for (int i = 0; i < 16; i++) T[i] = __fdividef(T[i], cs[i] + 1e-8f);
    }

    float tc = 0.f;
#pragma unroll
    for (int i = 0; i < 16; i++) tc = fmaf(T[i], Crow[i], tc);
#pragma unroll
    for (int s = 1; s < 16; s <<= 1) tc += __shfl_xor_sync(FULL, tc, s, 16);
    if (j == 0) {
        out_cost[b] = tc;
        out_sim[b]  = __fdividef(1.f, 1.f + __expf(tc));
    }
    float* To = out_T + (size_t)b * 256 + j * 16;
#pragma unroll
    for (int i = 0; i < 4; i++)
        *reinterpret_cast<float4*>(To + 4 * i) =
            make_float4(T[4 * i], T[4 * i + 1], T[4 * i + 2], T[4 * i + 3]);
}

// ---------------------------------------------------------------------------
extern "C" void kernel_launch(void* const* d_in, const int* in_sizes, int n_in,
                              void* d_out, int out_size)
{
    const float* slots_q = (const float*)d_in[0];
    const float* slots_r = (const float*)d_in[1];
    const float* mask_q  = (const float*)d_in[2];
    const float* mask_r  = (const float*)d_in[3];
    const float* W1      = (const float*)d_in[4];
    const float* b1      = (const float*)d_in[5];
    const float* W2      = (const float*)d_in[6];
    const float* b2      = (const float*)d_in[7];

    float* out      = (float*)d_out;
    float* out_sim  = out;
    float* out_T    = out_sim + B_;
    float* out_C    = out_T + (size_t)B_ * K_ * M_;
    float* out_cost = out_C + (size_t)B_ * K_ * M_;

    cudaFuncSetAttribute(gemm_fused, cudaFuncAttributeMaxDynamicSharedMemorySize, SMEM_SZ);
    cudaFuncSetAttribute(cost_kernel, cudaFuncAttributeMaxDynamicSharedMemorySize, COST_SMEM);

    reset_flags_kernel<<<1, 512>>>();
    split_w_kernel<<<128, 512>>>(W1, W2);
    gemm_fused<<<2048, 256, SMEM_SZ>>>(slots_q, slots_r, b1, b2);
    cost_kernel<<<B_ / COST_CB, 256, COST_SMEM>>>(out_C);
    sinkhorn_iter<<<B_ / 16, 256>>>(out_C, mask_q, mask_r, out_sim, out_T, out_cost);
}

// round 14
// speedup vs baseline: 1.0473x; 1.0292x over previous
#include <cuda_runtime.h>
#include <cuda_bf16.h>
#include <cstdint>
#include <math.h>

#define B_  2048
#define K_  16
#define M_  16
#define D_  256
#define NITER  20
#define MESHIT 3
#define RTOT   65536           // 2048*16 (q rows) + 2048*16 (r rows)

// ---------------- scratch (__device__ globals; no runtime alloc) ----------------
__device__ __nv_bfloat16 g_W1h[D_ * D_], g_W1l[D_ * D_];
__device__ __nv_bfloat16 g_W2h[D_ * D_], g_W2l[D_ * D_];
__device__ __nv_bfloat16 g_Hh[(size_t)RTOT * D_], g_Hl[(size_t)RTOT * D_];
__device__ float         g_P [(size_t)RTOT * D_];
__device__ int           g_flag [512];         // layer-1 completion per 128-row block
__device__ int           g_flag2[512];         // layer-2 completion per 128-row block

// ---------------- helpers ----------------
__device__ __forceinline__ uint32_t smem_u32(const void* p) {
    uint32_t a;
    asm("{ .reg .u64 t; cvta.to.shared.u64 t, %1; cvt.u32.u64 %0, t; }" : "=r"(a) : "l"(p));
    return a;
}
__device__ __forceinline__ void cp16(uint32_t dst, const void* src) {
    asm volatile("cp.async.cg.shared.global [%0], [%1], 16;" :: "r"(dst), "l"(src) : "memory");
}
__device__ __forceinline__ void cp_commit() {
    asm volatile("cp.async.commit_group;" ::: "memory");
}
__device__ __forceinline__ void cp_wait0() {
    asm volatile("cp.async.wait_group 0;" ::: "memory");
}
__device__ __forceinline__ void ldm_x4(uint32_t* r, uint32_t addr) {
    asm volatile("ldmatrix.sync.aligned.m8n8.x4.shared.b16 {%0,%1,%2,%3}, [%4];"
                 : "=r"(r[0]), "=r"(r[1]), "=r"(r[2]), "=r"(r[3]) : "r"(addr));
}
__device__ __forceinline__ void mma_bf16(float* d, const uint32_t* a, const uint32_t* b) {
    asm volatile(
        "mma.sync.aligned.m16n8k16.row.col.f32.bf16.bf16.f32 "
        "{%0,%1,%2,%3}, {%4,%5,%6,%7}, {%8,%9}, {%0,%1,%2,%3};"
        : "+f"(d[0]), "+f"(d[1]), "+f"(d[2]), "+f"(d[3])
        : "r"(a[0]), "r"(a[1]), "r"(a[2]), "r"(a[3]), "r"(b[0]), "r"(b[1]));
}
__device__ __forceinline__ void split2(float a, float b, uint32_t& hi, uint32_t& lo) {
    __nv_bfloat16 ha = __float2bfloat16_rn(a), hb = __float2bfloat16_rn(b);
    float la = a - __bfloat162float(ha);
    float lb = b - __bfloat162float(hb);
    __nv_bfloat162 H; H.x = ha; H.y = hb;
    __nv_bfloat162 L; L.x = __float2bfloat16_rn(la); L.y = __float2bfloat16_rn(lb);
    hi = *reinterpret_cast<uint32_t*>(&H);
    lo = *reinterpret_cast<uint32_t*>(&L);
}

// ---------------- prep: zero flags + split weights ----------------
__global__ void reset_flags_kernel() {
    if (threadIdx.x < 512) g_flag[threadIdx.x] = 0;
    else                   g_flag2[threadIdx.x - 512] = 0;
}

__global__ void split_w_kernel(const float* __restrict__ W1, const float* __restrict__ W2) {
    int i = blockIdx.x * blockDim.x + threadIdx.x;
    float w1 = W1[i];
    __nv_bfloat16 h1 = __float2bfloat16_rn(w1);
    g_W1h[i] = h1;
    g_W1l[i] = __float2bfloat16_rn(w1 - __bfloat162float(h1));
    float w2 = W2[i];
    __nv_bfloat16 h2 = __float2bfloat16_rn(w2);
    g_W2h[i] = h2;
    g_W2l[i] = __float2bfloat16_rn(w2 - __bfloat162float(h2));
}

// ---------------- mega kernel: L1 GEMM | L2 GEMM | cost, chained by flags --------
// bid < 1024:        layer-1 tile (bidx = bid>>1, coly = bid&1)
// 1024 <= bid <2048: layer-2 tile; spins g_flag[bidx]==2; publishes g_flag2
// bid >= 2048:       cost for batches {2c, 2c+1}, c = bid-2048;
//                    spins g_flag2[c>>2]==2 && g_flag2[256+(c>>2)]==2.
#define OFF_AH 0
#define OFF_AL 8192
#define OFF_BH 16384
#define OFF_BL 24576
#define STAGE  32768
#define OFF_BIAS 65536

#define COST_CB 2
#define CROW 258
#define COST_MAT (16 * CROW)
#define COST_SMEM ((COST_CB * 2 * COST_MAT + 2 * COST_CB * 16) * 4)   // 66304
#define SMEM_SZ  (COST_SMEM > 66048 ? COST_SMEM : 66048)

__device__ __forceinline__ uint32_t tile_addr(uint32_t base, int row, int c16) {
    int p = c16 ^ ((row >> 1) & 3);
    return base + row * 64 + p * 16;
}

__global__ void __launch_bounds__(256, 2) fused_all(
    const float* __restrict__ Aq, const float* __restrict__ Ar,
    const float* __restrict__ b1, const float* __restrict__ b2,
    float* __restrict__ out_C)
{
    extern __shared__ char smem[];
    const int tid = threadIdx.x;
    const int bid = blockIdx.x;
    const uint32_t FULL = 0xffffffffu;

    if (bid >= 2048) {
        // ================= cost branch (R11 body) =================
        float* sm = reinterpret_cast<float*>(smem);
        const int c  = bid - 2048;
        const int b0 = c * COST_CB;
        const int gblk = c >> 2;

        if (tid == 0) {
            while (atomicAdd(&g_flag2[gblk], 0) < 2) { }
            while (atomicAdd(&g_flag2[256 + gblk], 0) < 2) { }
            __threadfence();
        }
        __syncthreads();

#pragma unroll
        for (int it = 0; it < 16; it++) {
            int u   = tid + it * 256;
            int mat = u >> 10;
            int v   = u & 1023;
            int blb = mat >> 1, isr = mat & 1;
            int row = v >> 6, d = (v & 63) * 4;
            const float* src = g_P + ((size_t)(isr ? 32768 : 0) + (size_t)(b0 + blb) * 16 + row) * 256 + d;
            float4 x = *reinterpret_cast<const float4*>(src);
            float* dst = sm + (blb * 2 + isr) * COST_MAT + row * CROW + d;
            dst[0] = x.x; dst[1] = x.y; dst[2] = x.z; dst[3] = x.w;
        }
        __syncthreads();

        const int bl = tid >> 7, t = tid & 127;
        const float* q = sm + bl * 2 * COST_MAT;
        const float* r = q + COST_MAT;
        float* nq = sm + COST_CB * 2 * COST_MAT;
        float* nr = nq + COST_CB * 16;

        if (t < 64) {
            int row = t & 15;
            int h   = (t >> 4) & 1;
            int isr = (t >> 5) & 1;
            const float* src = (isr ? r : q) + row * CROW;
            float s0 = 0.f, s1 = 0.f;
#pragma unroll 8
            for (int d = 2 * h; d < 256; d += 4) {
                float2 x = *reinterpret_cast<const float2*>(src + d);
                s0 = fmaf(x.x, x.x, s0);
                s1 = fmaf(x.y, x.y, s1);
            }
            float s = s0 + s1;
            s += __shfl_xor_sync(FULL, s, 16);
            if (h == 0) (isr ? nr : nq)[bl * 16 + row] = s;
        }

        const int m2 = t & 7;
        const int dh = (t >> 3) & 1;
        const int k2 = t >> 4;
        const float* qa = q + (2 * k2) * CROW;
        const float* qb = qa + CROW;
        const float* ra = r + (2 * m2) * CROW;
        const float* rb = ra + CROW;
        float g00 = 0.f, g01 = 0.f, g10 = 0.f, g11 = 0.f;
#pragma unroll 8
        for (int d = 2 * dh; d < 256; d += 4) {
            float2 xa = *reinterpret_cast<const float2*>(qa + d);
            float2 xb = *reinterpret_cast<const float2*>(qb + d);
            float2 ya = *reinterpret_cast<const float2*>(ra + d);
            float2 yb = *reinterpret_cast<const float2*>(rb + d);
            g00 = fmaf(xa.x, ya.x, g00); g00 = fmaf(xa.y, ya.y, g00);
            g01 = fmaf(xa.x, yb.x, g01); g01 = fmaf(xa.y, yb.y, g01);
            g10 = fmaf(xb.x, ya.x, g10); g10 = fmaf(xb.y, ya.y, g10);
            g11 = fmaf(xb.x, yb.x, g11); g11 = fmaf(xb.y, yb.y, g11);
        }
        g00 += __shfl_xor_sync(FULL, g00, 8);
        g01 += __shfl_xor_sync(FULL, g01, 8);
        g10 += __shfl_xor_sync(FULL, g10, 8);
        g11 += __shfl_xor_sync(FULL, g11, 8);
        __syncthreads();

        if (dh == 0) {
            const float nqa = nq[bl * 16 + 2 * k2], nqb = nq[bl * 16 + 2 * k2 + 1];
            const float nra = nr[bl * 16 + 2 * m2], nrb = nr[bl * 16 + 2 * m2 + 1];
            float* Co = out_C + (size_t)(b0 + bl) * 256;
            Co[(2 * k2)     * 16 + 2 * m2]     = sqrtf(fmaxf(nqa + nra - 2.f * g00, 1e-6f));
            Co[(2 * k2)     * 16 + 2 * m2 + 1] = sqrtf(fmaxf(nqa + nrb - 2.f * g01, 1e-6f));
            Co[(2 * k2 + 1) * 16 + 2 * m2]     = sqrtf(fmaxf(nqb + nra - 2.f * g10, 1e-6f));
            Co[(2 * k2 + 1) * 16 + 2 * m2 + 1] = sqrtf(fmaxf(nqb + nrb - 2.f * g11, 1e-6f));
        }
        return;
    }

    // ================= GEMM branches =================
    const uint32_t sb = smem_u32(smem);
    const int w    = tid >> 5;
    const int lane = tid & 31;
    const bool layer1 = (bid < 1024);
    const int sub  = layer1 ? bid : bid - 1024;
    const int bidx = sub >> 1;
    const int col0 = (sub & 1) * 128;

    if (!layer1) {
        if (tid == 0) {
            while (atomicAdd(&g_flag[bidx], 0) < 2) { }
            __threadfence();
        }
        __syncthreads();
    }

    const __nv_bfloat16* Wh = layer1 ? g_W1h : g_W2h;
    const __nv_bfloat16* Wl = layer1 ? g_W1l : g_W2l;
    const float* bias = layer1 ? b1 : b2;
    const float* Asrc = nullptr;
    const __nv_bfloat16 *Ah = nullptr, *Al = nullptr;
    if (layer1) {
        Asrc = (bidx < 256) ? (Aq + (size_t)bidx * 128 * D_)
                            : (Ar + (size_t)(bidx - 256) * 128 * D_);
    } else {
        Ah = g_Hh + (size_t)bidx * 128 * D_;
        Al = g_Hl + (size_t)bidx * 128 * D_;
    }

    if (tid < 128) ((float*)(smem + OFF_BIAS))[tid] = bias[col0 + tid];

    const int lr   = tid >> 1;
    const int half = tid & 1;

    auto issue_loads = [&](int kc, int stage, float4* fa) {
        const uint32_t st = sb + stage * STAGE;
        const int k0 = kc * 32;
        {
            const __nv_bfloat16* sh = Wh + (size_t)(col0 + lr) * D_ + k0 + half * 16;
            const __nv_bfloat16* sl = Wl + (size_t)(col0 + lr) * D_ + k0 + half * 16;
            int c0 = half * 2;
            cp16(tile_addr(st + OFF_BH, lr, c0),     sh);
            cp16(tile_addr(st + OFF_BH, lr, c0 + 1), sh + 8);
            cp16(tile_addr(st + OFF_BL, lr, c0),     sl);
            cp16(tile_addr(st + OFF_BL, lr, c0 + 1), sl + 8);
        }
        if (!layer1) {
            const __nv_bfloat16* sh = Ah + (size_t)lr * D_ + k0 + half * 16;
            const __nv_bfloat16* sl = Al + (size_t)lr * D_ + k0 + half * 16;
            int c0 = half * 2;
            cp16(tile_addr(st + OFF_AH, lr, c0),     sh);
            cp16(tile_addr(st + OFF_AH, lr, c0 + 1), sh + 8);
            cp16(tile_addr(st + OFF_AL, lr, c0),     sl);
            cp16(tile_addr(st + OFF_AL, lr, c0 + 1), sl + 8);
        } else {
            const float4* p = reinterpret_cast<const float4*>(
                Asrc + (size_t)lr * D_ + k0 + half * 16);
            fa[0] = p[0]; fa[1] = p[1]; fa[2] = p[2]; fa[3] = p[3];
        }
        cp_commit();
    };
    auto sts_A = [&](int stage, const float4* fa) {
        const uint32_t st = sb + stage * STAGE;
        uint32_t h[8], l[8];
        split2(fa[0].x, fa[0].y, h[0], l[0]); split2(fa[0].z, fa[0].w, h[1], l[1]);
        split2(fa[1].x, fa[1].y, h[2], l[2]); split2(fa[1].z, fa[1].w, h[3], l[3]);
        split2(fa[2].x, fa[2].y, h[4], l[4]); split2(fa[2].z, fa[2].w, h[5], l[5]);
        split2(fa[3].x, fa[3].y, h[6], l[6]); split2(fa[3].z, fa[3].w, h[7], l[7]);
        int c0 = half * 2;
        *reinterpret_cast<uint4*>(smem + (tile_addr(st + OFF_AH, lr, c0)     - sb)) = make_uint4(h[0], h[1], h[2], h[3]);
        *reinterpret_cast<uint4*>(smem + (tile_addr(st + OFF_AH, lr, c0 + 1) - sb)) = make_uint4(h[4], h[5], h[6], h[7]);
        *reinterpret_cast<uint4*>(smem + (tile_addr(st + OFF_AL, lr, c0)     - sb)) = make_uint4(l[0], l[1], l[2], l[3]);
        *reinterpret_cast<uint4*>(smem + (tile_addr(st + OFF_AL, lr, c0 + 1) - sb)) = make_uint4(l[4], l[5], l[6], l[7]);
    };

    float4 fa[4];
    issue_loads(0, 0, fa);
    if (layer1) sts_A(0, fa);
    cp_wait0();
    __syncthreads();

    const int m0  = (w & 1) * 64;
    const int n0w = (w >> 1) * 32;
    float acc[4][4][4];
#pragma unroll
    for (int i = 0; i < 4; i++)
#pragma unroll
        for (int j = 0; j < 4; j++)
#pragma unroll
            for (int t2 = 0; t2 < 4; t2++) acc[i][j][t2] = 0.f;

    const int arow = m0 + (lane & 15);
    const int adc  = (lane >> 4) & 1;
    const int brow = n0w + ((lane >> 4) & 1) * 8 + (lane & 7);
    const int bdc  = (lane >> 3) & 1;

    for (int kc = 0; kc < 8; kc++) {
        const int cur = kc & 1, nxt = cur ^ 1;
        if (kc < 7) issue_loads(kc + 1, nxt, fa);

        const uint32_t st = sb + cur * STAGE;
#pragma unroll
        for (int ks = 0; ks < 2; ks++) {
            const int cb = ks * 2;
            uint32_t bh[8], bl[8], a[16];
#pragma unroll
            for (int pr = 0; pr < 2; pr++) {
                ldm_x4(bh + pr * 4, tile_addr(st + OFF_BH, brow + pr * 16, cb + bdc));
                ldm_x4(bl + pr * 4, tile_addr(st + OFF_BL, brow + pr * 16, cb + bdc));
            }
#pragma unroll
            for (int mt = 0; mt < 4; mt++)
                ldm_x4(a + mt * 4, tile_addr(st + OFF_AH, arow + mt * 16, cb + adc));
#pragma unroll
            for (int mt = 0; mt < 4; mt++)
#pragma unroll
                for (int nt = 0; nt < 4; nt++)
                    mma_bf16(acc[mt][nt], a + mt * 4, bh + nt * 2);
#pragma unroll
            for (int mt = 0; mt < 4; mt++)
#pragma unroll
                for (int nt = 0; nt < 4; nt++)
                    mma_bf16(acc[mt][nt], a + mt * 4, bl + nt * 2);
#pragma unroll
            for (int mt = 0; mt < 4; mt++)
                ldm_x4(a + mt * 4, tile_addr(st + OFF_AL, arow + mt * 16, cb + adc));
#pragma unroll
            for (int mt = 0; mt < 4; mt++)
#pragma unroll
                for (int nt = 0; nt < 4; nt++)
                    mma_bf16(acc[mt][nt], a + mt * 4, bh + nt * 2);
        }

        if (layer1 && kc < 7) sts_A(nxt, fa);
        cp_wait0();
        __syncthreads();
    }

    const float* sbias = (const float*)(smem + OFF_BIAS);
    const int g  = lane >> 2;
    const int tg = lane & 3;
#pragma unroll
    for (int mt = 0; mt < 4; mt++) {
        const int row0 = bidx * 128 + m0 + mt * 16 + g;
#pragma unroll
        for (int nt = 0; nt < 4; nt++) {
            const int ncl = n0w + nt * 8 + tg * 2;
            const int nc  = col0 + ncl;
            const float bb0 = sbias[ncl], bb1 = sbias[ncl + 1];
            float y0 = acc[mt][nt][0] + bb0, y1 = acc[mt][nt][1] + bb1;
            float y2 = acc[mt][nt][2] + bb0, y3 = acc[mt][nt][3] + bb1;
            if (layer1) {
                y0 = fmaxf(y0, 0.f); y1 = fmaxf(y1, 0.f);
                y2 = fmaxf(y2, 0.f); y3 = fmaxf(y3, 0.f);
                uint32_t h0, l0, h1, l1;
                split2(y0, y1, h0, l0);
                split2(y2, y3, h1, l1);
                *reinterpret_cast<uint32_t*>(g_Hh + (size_t)row0 * D_ + nc)       = h0;
                *reinterpret_cast<uint32_t*>(g_Hl + (size_t)row0 * D_ + nc)       = l0;
                *reinterpret_cast<uint32_t*>(g_Hh + (size_t)(row0 + 8) * D_ + nc) = h1;
                *reinterpret_cast<uint32_t*>(g_Hl + (size_t)(row0 + 8) * D_ + nc) = l1;
            } else {
                *reinterpret_cast<float2*>(g_P + (size_t)row0 * D_ + nc)       = make_float2(y0, y1);
                *reinterpret_cast<float2*>(g_P + (size_t)(row0 + 8) * D_ + nc) = make_float2(y2, y3);
            }
        }
    }

    __threadfence();
    __syncthreads();
    if (tid == 0) {
        if (layer1) atomicAdd(&g_flag[bidx], 1);
        else        atomicAdd(&g_flag2[bidx], 1);
    }
}

// ---------------- sinkhorn iterate: linear domain, half-warp per batch ----------------
__global__ void __launch_bounds__(256) sinkhorn_iter(
    const float* __restrict__ C, const float* __restrict__ mask_q,
    const float* __restrict__ mask_r,
    float* __restrict__ out_sim, float* __restrict__ out_T,
    float* __restrict__ out_cost)
{
    const int tid  = threadIdx.x;
    const int wrp  = tid >> 5;
    const int lane = tid & 31;
    const int half = lane >> 4;
    const int j    = lane & 15;
    const int b    = blockIdx.x * 16 + wrp * 2 + half;
    const uint32_t FULL = 0xffffffffu;

    const float* Cb = C + (size_t)b * 256;
    float Crow[16], Ccol[16];
#pragma unroll
    for (int i = 0; i < 4; i++) {
        float4 v = *reinterpret_cast<const float4*>(Cb + j * 16 + i * 4);
        Crow[4 * i] = v.x; Crow[4 * i + 1] = v.y; Crow[4 * i + 2] = v.z; Crow[4 * i + 3] = v.w;
    }
#pragma unroll
    for (int k = 0; k < 16; k++) Ccol[k] = Cb[k * 16 + j];

    float lmq = __logf(fmaxf(mask_q[b * 16 + j], 1e-8f));
    float lmr = __logf(fmaxf(mask_r[b * 16 + j], 1e-8f));
    float mq = lmq, mr = lmr;
#pragma unroll
    for (int s = 1; s < 16; s <<= 1) {
        mq = fmaxf(mq, __shfl_xor_sync(FULL, mq, s, 16));
        mr = fmaxf(mr, __shfl_xor_sync(FULL, mr, s, 16));
    }
    float eq = __expf(lmq - mq), er = __expf(lmr - mr);
#pragma unroll
    for (int s = 1; s < 16; s <<= 1) {
        eq += __shfl_xor_sync(FULL, eq, s, 16);
        er += __shfl_xor_sync(FULL, er, s, 16);
    }
    const float logmu = lmq - (mq + __logf(eq));
    const float lognu = lmr - (mr + __logf(er));

    float mv[16], nv[16];
#pragma unroll
    for (int i = 0; i < 16; i++) {
        mv[i] = __shfl_sync(FULL, logmu, i, 16);
        nv[i] = __shfl_sync(FULL, lognu, i, 16);
    }

    float Erow[16], Ecol[16];
#pragma unroll
    for (int i = 0; i < 16; i++) Erow[i] = -Crow[i] / 0.05f + logmu + nv[i];
    float mx = Erow[0];
#pragma unroll
    for (int i = 1; i < 16; i++) mx = fmaxf(mx, Erow[i]);
#pragma unroll
    for (int s = 1; s < 16; s <<= 1) mx = fmaxf(mx, __shfl_xor_sync(FULL, mx, s, 16));
#pragma unroll
    for (int i = 0; i < 16; i++) Erow[i] = __expf(Erow[i] - mx);
#pragma unroll
    for (int k = 0; k < 16; k++) Ecol[k] = __expf(-Ccol[k] / 0.05f + mv[k] + lognu - mx);

    float bv[16];
#pragma unroll
    for (int i = 0; i < 16; i++) bv[i] = 1.f;
    float a = 1.f;
    for (int it = 0; it < NITER; it++) {
        float s0 = 0.f, s1 = 0.f, s2 = 0.f, s3 = 0.f;
#pragma unroll
        for (int i = 0; i < 16; i += 4) {
            s0 = fmaf(Erow[i],     bv[i],     s0);
            s1 = fmaf(Erow[i + 1], bv[i + 1], s1);
            s2 = fmaf(Erow[i + 2], bv[i + 2], s2);
            s3 = fmaf(Erow[i + 3], bv[i + 3], s3);
        }
        a = __fdividef(1.f, (s0 + s1) + (s2 + s3));
        float av[16];
#pragma unroll
        for (int i = 0; i < 16; i++) av[i] = __shfl_sync(FULL, a, i, 16);
        float t0 = 0.f, t1 = 0.f, t2 = 0.f, t3 = 0.f;
#pragma unroll
        for (int k = 0; k < 16; k += 4) {
            t0 = fmaf(Ecol[k],     av[k],     t0);
            t1 = fmaf(Ecol[k + 1], av[k + 1], t1);
            t2 = fmaf(Ecol[k + 2], av[k + 2], t2);
            t3 = fmaf(Ecol[k + 3], av[k + 3], t3);
        }
        float bb = __fdividef(1.f, (t0 + t1) + (t2 + t3));
#pragma unroll
        for (int i = 0; i < 16; i++) bv[i] = __shfl_sync(FULL, bb, i, 16);
    }

    float T[16];
#pragma unroll
    for (int i = 0; i < 16; i++) T[i] = a * Erow[i] * bv[i];

#pragma unroll
    for (int it = 0; it < MESHIT; it++) {
        float rs = 0.f;
#pragma unroll
        for (int i = 0; i < 16; i++) { T[i] *= T[i]; rs += T[i]; }
        float inv = __fdividef(1.f, rs + 1e-8f);
        float cs[16];
#pragma unroll
        for (int i = 0; i < 16; i++) { T[i] *= inv; cs[i] = T[i]; }
#pragma unroll
        for (int s = 1; s < 16; s <<= 1)
#pragma unroll
            for (int i = 0; i < 16; i++) cs[i] += __shfl_xor_sync(FULL, cs[i], s, 16);
#pragma unroll
        for (int i = 0; i < 16; i++) T[i] = __fdividef(T[i], cs[i] + 1e-8f);
    }

    float tc = 0.f;
#pragma unroll
    for (int i = 0; i < 16; i++) tc = fmaf(T[i], Crow[i], tc);
#pragma unroll
    for (int s = 1; s < 16; s <<= 1) tc += __shfl_xor_sync(FULL, tc, s, 16);
    if (j == 0) {
        out_cost[b] = tc;
        out_sim[b]  = __fdividef(1.f, 1.f + __expf(tc));
    }
    float* To = out_T + (size_t)b * 256 + j * 16;
#pragma unroll
    for (int i = 0; i < 4; i++)
        *reinterpret_cast<float4*>(To + 4 * i) =
            make_float4(T[4 * i], T[4 * i + 1], T[4 * i + 2], T[4 * i + 3]);
}

// ---------------------------------------------------------------------------
extern "C" void kernel_launch(void* const* d_in, const int* in_sizes, int n_in,
                              void* d_out, int out_size)
{
    const float* slots_q = (const float*)d_in[0];
    const float* slots_r = (const float*)d_in[1];
    const float* mask_q  = (const float*)d_in[2];
    const float* mask_r  = (const float*)d_in[3];
    const float* W1      = (const float*)d_in[4];
    const float* b1      = (const float*)d_in[5];
    const float* W2      = (const float*)d_in[6];
    const float* b2      = (const float*)d_in[7];

    float* out      = (float*)d_out;
    float* out_sim  = out;
    float* out_T    = out_sim + B_;
    float* out_C    = out_T + (size_t)B_ * K_ * M_;
    float* out_cost = out_C + (size_t)B_ * K_ * M_;

    cudaFuncSetAttribute(fused_all, cudaFuncAttributeMaxDynamicSharedMemorySize, SMEM_SZ);

    reset_flags_kernel<<<1, 1024>>>();
    split_w_kernel<<<128, 512>>>(W1, W2);
    fused_all<<<3072, 256, SMEM_SZ>>>(slots_q, slots_r, b1, b2, out_C);
    sinkhorn_iter<<<B_ / 16, 256>>>(out_C, mask_q, mask_r, out_sim, out_T, out_cost);
}